// round 4
// baseline (speedup 1.0000x reference)
#include <cuda_runtime.h>
#include <math.h>
#include <stdint.h>

// ---------------- problem dims ----------------
constexpr int cB   = 2;
constexpr int cS   = 2048;
constexpr int cE   = 2048;
constexpr int cH   = 2688;
constexpr int c2H  = 2 * cH;
constexpr int cNH  = 4;
constexpr int cDH  = 672;   // cH / cNH
constexpr int cKS  = 4;
constexpr int cNPH = 672;   // cH / 4
constexpr long long cBS  = (long long)cB * cS;        // 4096
constexpr long long cBSH = cBS * cH;                  // 11,010,048
constexpr long long cSCORES = (long long)cB * cNH * cS * cS; // 33,554,432
constexpr int cBHS = cB * cNH * cS;                   // 16384

// ---------------- device scratch ----------------
__device__ float g_xmz[cBS * (long long)c2H];   // [BS][2H]: xm | z
__device__ float g_xca[cBSH];
__device__ float g_q  [cBSH];
__device__ float g_k  [cBSH];
__device__ float g_v  [cBSH];
__device__ float g_h  [cBSH];
__device__ float g_hs [cBSH];
__device__ float g_scores[cSCORES];
__device__ float g_ipre[cBHS];
__device__ float g_fpre[cBHS];
__device__ float g_cs  [cBHS];
__device__ float g_a   [cBHS];
__device__ float g_pm  [cBHS];
__device__ float g_rs  [cBHS];
__device__ float g_nsum[cBHS];

// ---------------- helpers ----------------
__device__ __forceinline__ uint32_t f2tf32(float x) {
    uint32_t r;
    asm("cvt.rna.tf32.f32 %0, %1;" : "=r"(r) : "f"(x));
    return r;
}

__device__ __forceinline__ void cp16(uint32_t saddr, const void* gptr, int bytes) {
    asm volatile("cp.async.cg.shared.global [%0], [%1], 16, %2;\n"
                 :: "r"(saddr), "l"(gptr), "r"(bytes));
}
__device__ __forceinline__ void cp_commit() { asm volatile("cp.async.commit_group;\n" ::: "memory"); }
__device__ __forceinline__ void cp_wait0()  { asm volatile("cp.async.wait_group 0;\n" ::: "memory"); }

#define MMA_TF32(d, a, b)                                                      \
    asm volatile(                                                              \
        "mma.sync.aligned.m16n8k8.row.col.f32.tf32.tf32.f32 "                  \
        "{%0,%1,%2,%3},{%4,%5,%6,%7},{%8,%9},{%0,%1,%2,%3};\n"                 \
        : "+f"(d[0]), "+f"(d[1]), "+f"(d[2]), "+f"(d[3])                       \
        : "r"(a[0]), "r"(a[1]), "r"(a[2]), "r"(a[3]), "r"(b[0]), "r"(b[1]))

// ---------------- tf32 tensor-core GEMM (cp.async double buffered) ---------
// C[M,N] = epilogue(A@B). A row-major MxK. B: KxN (transB=0) or NxK (transB=1).
// Batched via blockIdx.z with two-level strides. M%128==0, K%16==0, N%4==0.
// mode 0: C = alpha * acc
// mode 1: scores: C = (n<=m) ? acc*alpha*exp(p1[n]-p2[m]) : 0; fully-masked
//         tiles skipped; per-row sums atomically accumulated into p3.
// mode 2: row scale: C = acc * p1[m]; K limited to tileM+128 (A lower-tri).
#define BM 128
#define BN 128
#define BK 16
#define ASTR 20    // BK + 4
#define BSTR 136   // BN + 8 (136 mod 32 == 8 -> conflict-free NN frag loads)

__global__ __launch_bounds__(256)
void tgemm_kernel(int M, int N, int K,
                  const float* __restrict__ A, int lda, long long sAb, long long sAn,
                  const float* __restrict__ B, int ldb, long long sBb, long long sBn,
                  float* __restrict__ C, int ldc, long long sCb, long long sCn,
                  int nhd, int transB, int mode, float alpha,
                  const float* __restrict__ p1, const float* __restrict__ p2,
                  float* __restrict__ p3, int pstr)
{
    const int z  = blockIdx.z;
    const int zb = z / nhd, zn = z % nhd;
    A += zb * sAb + zn * sAn;
    B += zb * sBb + zn * sBn;
    C += zb * sCb + zn * sCn;

    const int tileM = blockIdx.y * BM;
    const int tileN = blockIdx.x * BN;
    if (mode == 1 && tileN > tileM + BM - 1) return;   // fully masked tile

    const int t    = threadIdx.x;
    const int lane = t & 31;
    const int warp = t >> 5;
    const int g    = lane >> 2;     // 0..7
    const int t4   = lane & 3;      // 0..3
    const int wm   = (warp & 1) * 64;
    const int wn   = (warp >> 1) * 32;

    __shared__ float As[2][BM * ASTR];
    __shared__ float Bs[2][BM * ASTR + 128];  // NT: 128*20; NN: 16*136=2176 ok

    float acc[4][4][4];
#pragma unroll
    for (int i = 0; i < 4; i++)
#pragma unroll
        for (int j = 0; j < 4; j++)
#pragma unroll
            for (int r = 0; r < 4; r++) acc[i][j][r] = 0.f;

    int Kend = K;
    if (mode == 2) { int lim = tileM + BM; Kend = lim < K ? lim : K; }
    const int nIter = Kend / BK;

    uint32_t sA[2], sB[2];
    sA[0] = (uint32_t)__cvta_generic_to_shared(&As[0][0]);
    sA[1] = (uint32_t)__cvta_generic_to_shared(&As[1][0]);
    sB[0] = (uint32_t)__cvta_generic_to_shared(&Bs[0][0]);
    sB[1] = (uint32_t)__cvta_generic_to_shared(&Bs[1][0]);

    // per-thread owned smem word offsets (for in-place tf32 cvt after cp.async)
    int aOff[2], bOff[2];
    {
        int c0 = t, c1 = t + 256;
        aOff[0] = (c0 >> 2) * ASTR + (c0 & 3) * 4;
        aOff[1] = (c1 >> 2) * ASTR + (c1 & 3) * 4;
        if (!transB) {
            bOff[0] = (c0 >> 5) * BSTR + (c0 & 31) * 4;
            bOff[1] = (c1 >> 5) * BSTR + (c1 & 31) * 4;
        } else {
            bOff[0] = aOff[0];
            bOff[1] = aOff[1];
        }
    }

    auto loadTiles = [&](int stg, int k0) {
#pragma unroll
        for (int hh = 0; hh < 2; hh++) {
            int c   = t + hh * 256;
            int row = c >> 2;
            int kc  = (c & 3) * 4;
            const float* gp = &A[(long long)(tileM + row) * lda + k0 + kc];
            cp16(sA[stg] + (row * ASTR + kc) * 4, gp, 16);
        }
        if (!transB) {
#pragma unroll
            for (int hh = 0; hh < 2; hh++) {
                int c  = t + hh * 256;
                int kr = c >> 5;
                int n4 = (c & 31) * 4;
                int gn = tileN + n4;
                int ok = (gn < N);
                const float* gp = &B[(long long)(k0 + kr) * ldb + (ok ? gn : 0)];
                cp16(sB[stg] + (kr * BSTR + n4) * 4, gp, ok ? 16 : 0);
            }
        } else {
#pragma unroll
            for (int hh = 0; hh < 2; hh++) {
                int c   = t + hh * 256;
                int row = c >> 2;
                int kc  = (c & 3) * 4;
                const float* gp = &B[(long long)(tileN + row) * ldb + k0 + kc];
                cp16(sB[stg] + (row * ASTR + kc) * 4, gp, 16);
            }
        }
        cp_commit();
    };

    // convert own-written elements to tf32 in place
    auto cvtOwned = [&](int stg) {
        float* Ab = As[stg];
        float* Bb = Bs[stg];
#pragma unroll
        for (int hh = 0; hh < 2; hh++) {
            float4* pa = reinterpret_cast<float4*>(Ab + aOff[hh]);
            float4 va = *pa;
            va.x = __uint_as_float(f2tf32(va.x));
            va.y = __uint_as_float(f2tf32(va.y));
            va.z = __uint_as_float(f2tf32(va.z));
            va.w = __uint_as_float(f2tf32(va.w));
            *pa = va;
            float4* pb = reinterpret_cast<float4*>(Bb + bOff[hh]);
            float4 vb = *pb;
            vb.x = __uint_as_float(f2tf32(vb.x));
            vb.y = __uint_as_float(f2tf32(vb.y));
            vb.z = __uint_as_float(f2tf32(vb.z));
            vb.w = __uint_as_float(f2tf32(vb.w));
            *pb = vb;
        }
    };

    loadTiles(0, 0);
    cp_wait0();
    cvtOwned(0);
    __syncthreads();

    for (int it = 0; it < nIter; it++) {
        const int s  = it & 1;
        const int kn = (it + 1) * BK;
        const bool more = (kn < Kend);
        if (more) loadTiles(s ^ 1, kn);

        const float* Asb = As[s];
        const float* Bsb = Bs[s];
#pragma unroll
        for (int ks = 0; ks < BK; ks += 8) {
            uint32_t af[4][4], bf[4][2];
#pragma unroll
            for (int i = 0; i < 4; i++) {
                int m0 = wm + i * 16 + g;
                af[i][0] = __float_as_uint(Asb[(m0    ) * ASTR + ks + t4    ]);
                af[i][1] = __float_as_uint(Asb[(m0 + 8) * ASTR + ks + t4    ]);
                af[i][2] = __float_as_uint(Asb[(m0    ) * ASTR + ks + t4 + 4]);
                af[i][3] = __float_as_uint(Asb[(m0 + 8) * ASTR + ks + t4 + 4]);
            }
#pragma unroll
            for (int j = 0; j < 4; j++) {
                int n0 = wn + j * 8 + g;
                if (transB) {
                    bf[j][0] = __float_as_uint(Bsb[n0 * ASTR + ks + t4    ]);
                    bf[j][1] = __float_as_uint(Bsb[n0 * ASTR + ks + t4 + 4]);
                } else {
                    bf[j][0] = __float_as_uint(Bsb[(ks + t4    ) * BSTR + n0]);
                    bf[j][1] = __float_as_uint(Bsb[(ks + t4 + 4) * BSTR + n0]);
                }
            }
#pragma unroll
            for (int i = 0; i < 4; i++)
#pragma unroll
                for (int j = 0; j < 4; j++)
                    MMA_TF32(acc[i][j], af[i], bf[j]);
        }

        if (more) { cp_wait0(); cvtOwned(s ^ 1); }
        __syncthreads();
    }

    // ---- epilogue ----
    const long long zoff = (long long)z * pstr;
    float p1v[8];
    if (mode == 1) {
#pragma unroll
        for (int j = 0; j < 4; j++) {
            int gn = tileN + wn + j * 8 + t4 * 2;
            p1v[2 * j]     = p1[zoff + gn];
            p1v[2 * j + 1] = p1[zoff + gn + 1];
        }
    }
#pragma unroll
    for (int i = 0; i < 4; i++) {
        int gmBase = tileM + wm + i * 16 + g;
#pragma unroll
        for (int half = 0; half < 2; half++) {
            int gm = gmBase + half * 8;
            float pmv = 0.f, rsv = 1.f;
            if (mode == 1)      pmv = p2[zoff + gm];
            else if (mode == 2) rsv = p1[zoff + gm];
            float* Crow = C + (long long)gm * ldc;
            float rsum = 0.f;
#pragma unroll
            for (int j = 0; j < 4; j++) {
                int gn = tileN + wn + j * 8 + t4 * 2;
                if (gn >= N) continue;
                float v0 = acc[i][j][half * 2 + 0];
                float v1 = acc[i][j][half * 2 + 1];
                if (mode == 1) {
                    v0 = (gn     <= gm) ? v0 * alpha * __expf(p1v[2 * j    ] - pmv) : 0.f;
                    v1 = (gn + 1 <= gm) ? v1 * alpha * __expf(p1v[2 * j + 1] - pmv) : 0.f;
                    rsum += v0 + v1;
                } else if (mode == 2) {
                    v0 *= rsv; v1 *= rsv;
                } else {
                    v0 *= alpha; v1 *= alpha;
                }
                *reinterpret_cast<float2*>(&Crow[gn]) = make_float2(v0, v1);
            }
            if (mode == 1) {
                rsum += __shfl_xor_sync(0xffffffffu, rsum, 1);
                rsum += __shfl_xor_sync(0xffffffffu, rsum, 2);
                if (t4 == 0) atomicAdd(&p3[zoff + gm], rsum);
            }
        }
    }
}

// ---------------- depthwise causal conv + SiLU (xm in xmz, stride 2H) ------
__global__ void conv_silu_kernel(const float* __restrict__ xmz,
                                 const float* __restrict__ w,
                                 const float* __restrict__ bias,
                                 float* __restrict__ xca)
{
    long long idx = (long long)blockIdx.x * blockDim.x + threadIdx.x;
    if (idx >= cBSH) return;
    int h = (int)(idx % cH);
    long long bs = idx / cH;
    int s = (int)(bs % cS);
    long long rowbase = (bs - s) * c2H + h;
    float acc = bias[h];
#pragma unroll
    for (int tt = 0; tt < cKS; tt++) {
        int sp = s - (cKS - 1) + tt;
        if (sp >= 0) acc += xmz[rowbase + (long long)sp * c2H] * w[tt * cH + h];
    }
    float sg = 1.f / (1.f + __expf(-acc));
    xca[idx] = acc * sg;
}

// ---------------- headwise 4x4 projections ----------------
__global__ void headwise_kernel(const float* __restrict__ xca,
                                const float* __restrict__ xmz,
                                const float* __restrict__ Wq,
                                const float* __restrict__ Wk,
                                const float* __restrict__ Wv,
                                float* __restrict__ q,
                                float* __restrict__ k,
                                float* __restrict__ v)
{
    long long idx = (long long)blockIdx.x * blockDim.x + threadIdx.x;
    long long total = cBS * (long long)cNPH;
    if (idx >= total) return;
    int p = (int)(idx % cNPH);
    long long bs = idx / cNPH;
    long long base = bs * cH + p * 4;
    float4 xa = *reinterpret_cast<const float4*>(xca + base);
    float4 xv = *reinterpret_cast<const float4*>(xmz + bs * c2H + p * 4);
    const float4* wq4 = reinterpret_cast<const float4*>(Wq + p * 16);
    const float4* wk4 = reinterpret_cast<const float4*>(Wk + p * 16);
    const float4* wv4 = reinterpret_cast<const float4*>(Wv + p * 16);
    float4 q0 = wq4[0], q1 = wq4[1], q2 = wq4[2], q3 = wq4[3];
    float4 k0 = wk4[0], k1 = wk4[1], k2 = wk4[2], k3 = wk4[3];
    float4 v0 = wv4[0], v1 = wv4[1], v2 = wv4[2], v3 = wv4[3];
    float4 qo, ko, vo;
    qo.x = xa.x*q0.x + xa.y*q1.x + xa.z*q2.x + xa.w*q3.x;
    qo.y = xa.x*q0.y + xa.y*q1.y + xa.z*q2.y + xa.w*q3.y;
    qo.z = xa.x*q0.z + xa.y*q1.z + xa.z*q2.z + xa.w*q3.z;
    qo.w = xa.x*q0.w + xa.y*q1.w + xa.z*q2.w + xa.w*q3.w;
    ko.x = xa.x*k0.x + xa.y*k1.x + xa.z*k2.x + xa.w*k3.x;
    ko.y = xa.x*k0.y + xa.y*k1.y + xa.z*k2.y + xa.w*k3.y;
    ko.z = xa.x*k0.z + xa.y*k1.z + xa.z*k2.z + xa.w*k3.z;
    ko.w = xa.x*k0.w + xa.y*k1.w + xa.z*k2.w + xa.w*k3.w;
    vo.x = xv.x*v0.x + xv.y*v1.x + xv.z*v2.x + xv.w*v3.x;
    vo.y = xv.x*v0.y + xv.y*v1.y + xv.z*v2.y + xv.w*v3.y;
    vo.z = xv.x*v0.z + xv.y*v1.z + xv.z*v2.z + xv.w*v3.z;
    vo.w = xv.x*v0.w + xv.y*v1.w + xv.z*v2.w + xv.w*v3.w;
    *reinterpret_cast<float4*>(q + base) = qo;
    *reinterpret_cast<float4*>(k + base) = ko;
    *reinterpret_cast<float4*>(v + base) = vo;
}

// ---------------- gate projections (8 rows / block) ----------------
#define GROWS 8
__global__ __launch_bounds__(256)
void gates_kernel(const float* __restrict__ q, const float* __restrict__ k,
                  const float* __restrict__ v,
                  const float* __restrict__ Wig, const float* __restrict__ big,
                  const float* __restrict__ Wfg, const float* __restrict__ bfg,
                  float* __restrict__ ipre, float* __restrict__ fpre)
{
    int bs0 = blockIdx.x * GROWS;
    int t   = threadIdx.x;
    float ai[GROWS][4], afr[GROWS][4];
#pragma unroll
    for (int rw = 0; rw < GROWS; rw++)
#pragma unroll
        for (int n = 0; n < 4; n++) { ai[rw][n] = 0.f; afr[rw][n] = 0.f; }

    for (int r = t; r < 3 * cH; r += 256) {
        float4 wi = *reinterpret_cast<const float4*>(Wig + (long long)r * 4);
        float4 wf = *reinterpret_cast<const float4*>(Wfg + (long long)r * 4);
        const float* src;
        int col;
        if (r < cH)          { src = q; col = r; }
        else if (r < 2 * cH) { src = k; col = r - cH; }
        else                 { src = v; col = r - 2 * cH; }
#pragma unroll
        for (int rw = 0; rw < GROWS; rw++) {
            float val = src[(long long)(bs0 + rw) * cH + col];
            ai[rw][0] += val * wi.x; ai[rw][1] += val * wi.y;
            ai[rw][2] += val * wi.z; ai[rw][3] += val * wi.w;
            afr[rw][0] += val * wf.x; afr[rw][1] += val * wf.y;
            afr[rw][2] += val * wf.z; afr[rw][3] += val * wf.w;
        }
    }

    __shared__ float red[8][256];
    for (int rw = 0; rw < GROWS; rw++) {
#pragma unroll
        for (int n = 0; n < 4; n++) { red[n][t] = ai[rw][n]; red[4 + n][t] = afr[rw][n]; }
        __syncthreads();
        for (int o = 128; o > 0; o >>= 1) {
            if (t < o) {
#pragma unroll
                for (int m = 0; m < 8; m++) red[m][t] += red[m][t + o];
            }
            __syncthreads();
        }
        if (t == 0) {
            int bs = bs0 + rw;
            int b = bs / cS, s = bs % cS;
#pragma unroll
            for (int n = 0; n < 4; n++) {
                ipre[(long long)(b * cNH + n) * cS + s] = red[n][0] + big[n];
                fpre[(long long)(b * cNH + n) * cS + s] = red[4 + n][0] + bfg[n];
            }
        }
        __syncthreads();
    }
}

// ---------------- scan: cumsum(logsigmoid(f)), a = i - cs, prefix-max(a) ----
__global__ __launch_bounds__(256)
void scan_kernel(const float* __restrict__ ipre, const float* __restrict__ fpre,
                 float* __restrict__ cs, float* __restrict__ aArr,
                 float* __restrict__ pm, float* __restrict__ nsum)
{
    int bh = blockIdx.x;
    int t  = threadIdx.x;
    const float* fp = fpre + (long long)bh * cS;
    const float* ip = ipre + (long long)bh * cS;

    float loc[8];
    float sum = 0.f;
#pragma unroll
    for (int u = 0; u < 8; u++) {
        int j = t * 8 + u;
        float f = fp[j];
        float lf = fminf(f, 0.f) - log1pf(expf(-fabsf(f)));
        sum += lf;
        loc[u] = sum;
    }
    __shared__ float part[256];
    part[t] = sum;
    __syncthreads();
    for (int off = 1; off < 256; off <<= 1) {
        float vv = (t >= off) ? part[t - off] : 0.f;
        __syncthreads();
        part[t] += vv;
        __syncthreads();
    }
    float excl = part[t] - sum;

    float lmax[8];
    float amax = -1e30f;
#pragma unroll
    for (int u = 0; u < 8; u++) {
        int j = t * 8 + u;
        float csj = excl + loc[u];
        cs[(long long)bh * cS + j] = csj;
        float aj = ip[j] - csj;
        aArr[(long long)bh * cS + j] = aj;
        nsum[(long long)bh * cS + j] = 0.f;
        amax = fmaxf(amax, aj);
        lmax[u] = amax;
    }
    __syncthreads();
    part[t] = amax;
    __syncthreads();
    for (int off = 1; off < 256; off <<= 1) {
        float vv = (t >= off) ? part[t - off] : -1e30f;
        __syncthreads();
        part[t] = fmaxf(part[t], vv);
        __syncthreads();
    }
    float exmax = (t > 0) ? part[t - 1] : -1e30f;
#pragma unroll
    for (int u = 0; u < 8; u++) {
        int j = t * 8 + u;
        pm[(long long)bh * cS + j] = fmaxf(exmax, lmax[u]);
    }
}

// ---------------- finalize n -> rs ----------------
__global__ void nfin_kernel(const float* __restrict__ nsum,
                            const float* __restrict__ cs, const float* __restrict__ pm,
                            float* __restrict__ rs)
{
    int idx = blockIdx.x * blockDim.x + threadIdx.x;
    if (idx >= cBHS) return;
    float m = cs[idx] + pm[idx];
    float n = fmaxf(fabsf(nsum[idx]), __expf(-m));
    rs[idx] = 1.f / (n + 1e-6f);
}

// ---------------- multi-head LN + skip + z-gate ----------------
__global__ __launch_bounds__(256)
void ln_kernel(const float* __restrict__ hbuf, const float* __restrict__ xca,
               const float* __restrict__ xmz, const float* __restrict__ norm_w,
               const float* __restrict__ skip, float* __restrict__ hs)
{
    int s  = blockIdx.x;
    int bh = blockIdx.y;
    int t  = threadIdx.x;
    int b = bh / cNH, n = bh % cNH;
    const float* hrow = hbuf + ((long long)bh * cS + s) * cDH;

    float sum = 0.f, ss = 0.f;
    for (int d = t; d < cDH; d += 256) {
        float v = hrow[d];
        sum += v; ss += v * v;
    }
    __shared__ float r1[256], r2[256];
    r1[t] = sum; r2[t] = ss;
    __syncthreads();
    for (int o = 128; o > 0; o >>= 1) {
        if (t < o) { r1[t] += r1[t + o]; r2[t] += r2[t + o]; }
        __syncthreads();
    }
    float mean = r1[0] / cDH;
    float var  = r2[0] / cDH - mean * mean;
    float inv  = rsqrtf(var + 1e-5f);

    long long bsRow = (long long)b * cS + s;
    long long xbase = bsRow * cH;
    long long zbase = bsRow * c2H + cH;
    for (int d = t; d < cDH; d += 256) {
        int col = n * cDH + d;
        float hn = (hrow[d] - mean) * inv * norm_w[col];
        float hk = hn + skip[col] * xca[xbase + col];
        float zv = xmz[zbase + col];
        float sz = zv / (1.f + __expf(-zv));
        hs[xbase + col] = hk * sz;
    }
}

// ---------------- launch ----------------
extern "C" void kernel_launch(void* const* d_in, const int* in_sizes, int n_in,
                              void* d_out, int out_size)
{
    const float* x      = (const float*)d_in[0];
    const float* W_in   = (const float*)d_in[1];
    const float* conv_w = (const float*)d_in[2];
    const float* conv_b = (const float*)d_in[3];
    const float* Wq     = (const float*)d_in[4];
    const float* Wk     = (const float*)d_in[5];
    const float* Wv     = (const float*)d_in[6];
    const float* W_ig   = (const float*)d_in[7];
    const float* b_ig   = (const float*)d_in[8];
    const float* W_fg   = (const float*)d_in[9];
    const float* b_fg   = (const float*)d_in[10];
    const float* norm_w = (const float*)d_in[11];
    const float* skip   = (const float*)d_in[12];
    const float* W_out  = (const float*)d_in[13];
    float* out = (float*)d_out;

    float *p_xmz, *p_xca, *p_q, *p_k, *p_v, *p_h, *p_hs, *p_sc;
    float *p_ipre, *p_fpre, *p_cs, *p_a, *p_pm, *p_rs, *p_ns;
    cudaGetSymbolAddress((void**)&p_xmz, g_xmz);
    cudaGetSymbolAddress((void**)&p_xca, g_xca);
    cudaGetSymbolAddress((void**)&p_q,   g_q);
    cudaGetSymbolAddress((void**)&p_k,   g_k);
    cudaGetSymbolAddress((void**)&p_v,   g_v);
    cudaGetSymbolAddress((void**)&p_h,   g_h);
    cudaGetSymbolAddress((void**)&p_hs,  g_hs);
    cudaGetSymbolAddress((void**)&p_sc,  g_scores);
    cudaGetSymbolAddress((void**)&p_ipre, g_ipre);
    cudaGetSymbolAddress((void**)&p_fpre, g_fpre);
    cudaGetSymbolAddress((void**)&p_cs,  g_cs);
    cudaGetSymbolAddress((void**)&p_a,   g_a);
    cudaGetSymbolAddress((void**)&p_pm,  g_pm);
    cudaGetSymbolAddress((void**)&p_rs,  g_rs);
    cudaGetSymbolAddress((void**)&p_ns,  g_nsum);

    const int M0 = (int)cBS;  // 4096

    // 1) x @ W_in -> xmz (single merged GEMM, N = 2H)
    {
        dim3 grid(c2H / BN, M0 / BM, 1);
        tgemm_kernel<<<grid, 256>>>(M0, c2H, cE,
            x, cE, 0, 0,
            W_in, c2H, 0, 0,
            p_xmz, c2H, 0, 0,
            1, 0, 0, 1.0f, nullptr, nullptr, nullptr, 0);
    }

    // 2) depthwise causal conv + SiLU
    {
        long long total = cBSH;
        int blocks = (int)((total + 255) / 256);
        conv_silu_kernel<<<blocks, 256>>>(p_xmz, conv_w, conv_b, p_xca);
    }

    // 3) headwise q/k/v
    {
        long long total = cBS * (long long)cNPH;
        int blocks = (int)((total + 255) / 256);
        headwise_kernel<<<blocks, 256>>>(p_xca, p_xmz, Wq, Wk, Wv, p_q, p_k, p_v);
    }

    // 4) gates
    gates_kernel<<<M0 / GROWS, 256>>>(p_q, p_k, p_v, W_ig, b_ig, W_fg, b_fg, p_ipre, p_fpre);

    // 5) scan (also zeroes nsum)
    scan_kernel<<<cB * cNH, 256>>>(p_ipre, p_fpre, p_cs, p_a, p_pm, p_ns);

    // 6) scores = (q k^T / sqrt(DH)) * exp(a_j - pm_i), causal, + fused row sums
    {
        dim3 grid(cS / BN, cS / BM, cB * cNH);
        float alpha = 1.0f / sqrtf((float)cDH);
        tgemm_kernel<<<grid, 256>>>(cS, cS, cDH,
            p_q, cH, (long long)cS * cH, (long long)cDH,
            p_k, cH, (long long)cS * cH, (long long)cDH,
            p_sc, cS, (long long)cNH * cS * cS, (long long)cS * cS,
            cNH, 1, 1, alpha, p_a, p_pm, p_ns, cS);
    }

    // 7) finalize rs
    nfin_kernel<<<(cBHS + 255) / 256, 256>>>(p_ns, p_cs, p_pm, p_rs);

    // 8) h = diag(rs) * scores @ v   (causal K-limit)
    {
        dim3 grid((cDH + BN - 1) / BN, cS / BM, cB * cNH);
        tgemm_kernel<<<grid, 256>>>(cS, cDH, cS,
            p_sc, cS, (long long)cNH * cS * cS, (long long)cS * cS,
            p_v, cH, (long long)cS * cH, (long long)cDH,
            p_h, cDH, (long long)cNH * cS * cDH, (long long)cS * cDH,
            cNH, 0, 2, 1.0f, p_rs, nullptr, nullptr, cS);
    }

    // 9) LN + skip + z gate
    {
        dim3 grid(cS, cB * cNH);
        ln_kernel<<<grid, 256>>>(p_h, p_xca, p_xmz, norm_w, skip, p_hs);
    }

    // 10) out = hs @ W_out
    {
        dim3 grid(cE / BN, M0 / BM, 1);
        tgemm_kernel<<<grid, 256>>>(M0, cE, cH,
            p_hs, cH, 0, 0,
            W_out, cE, 0, 0,
            out, cE, 0, 0,
            1, 0, 0, 1.0f, nullptr, nullptr, nullptr, 0);
    }
}

// round 5
// speedup vs baseline: 1.0446x; 1.0446x over previous
#include <cuda_runtime.h>
#include <math.h>
#include <stdint.h>

// ---------------- problem dims ----------------
constexpr int cB   = 2;
constexpr int cS   = 2048;
constexpr int cE   = 2048;
constexpr int cH   = 2688;
constexpr int c2H  = 2 * cH;
constexpr int cNH  = 4;
constexpr int cDH  = 672;   // cH / cNH
constexpr int cKS  = 4;
constexpr int cNPH = 672;   // cH / 4
constexpr long long cBS  = (long long)cB * cS;        // 4096
constexpr long long cBSH = cBS * cH;                  // 11,010,048
constexpr long long cSCORES = (long long)cB * cNH * cS * cS; // 33,554,432
constexpr int cBHS = cB * cNH * cS;                   // 16384

// ---------------- device scratch ----------------
__device__ float g_xmz[cBS * (long long)c2H];   // [BS][2H]: xm | z
__device__ float g_xca[cBSH];
__device__ float g_q  [cBSH];
__device__ float g_k  [cBSH];
__device__ float g_v  [cBSH];
__device__ float g_h  [cBSH];
__device__ float g_hs [cBSH];
__device__ float g_scores[cSCORES];
__device__ float g_ipre[cBHS];
__device__ float g_fpre[cBHS];
__device__ float g_cs  [cBHS];
__device__ float g_a   [cBHS];
__device__ float g_pm  [cBHS];
__device__ float g_rs  [cBHS];
__device__ float g_nsum[cBHS];

// ---------------- helpers ----------------
__device__ __forceinline__ uint32_t f2tf32(float x) {
    uint32_t r;
    asm("cvt.rna.tf32.f32 %0, %1;" : "=r"(r) : "f"(x));
    return r;
}

__device__ __forceinline__ void cp16(uint32_t saddr, const void* gptr, int bytes) {
    asm volatile("cp.async.cg.shared.global [%0], [%1], 16, %2;\n"
                 :: "r"(saddr), "l"(gptr), "r"(bytes));
}
__device__ __forceinline__ void cp_commit() { asm volatile("cp.async.commit_group;\n" ::: "memory"); }
__device__ __forceinline__ void cp_wait0()  { asm volatile("cp.async.wait_group 0;\n" ::: "memory"); }

#define MMA_TF32(d, a, b)                                                      \
    asm volatile(                                                              \
        "mma.sync.aligned.m16n8k8.row.col.f32.tf32.tf32.f32 "                  \
        "{%0,%1,%2,%3},{%4,%5,%6,%7},{%8,%9},{%0,%1,%2,%3};\n"                 \
        : "+f"(d[0]), "+f"(d[1]), "+f"(d[2]), "+f"(d[3])                       \
        : "r"(a[0]), "r"(a[1]), "r"(a[2]), "r"(a[3]), "r"(b[0]), "r"(b[1]))

// ---------------- tf32 tensor-core GEMM (cp.async double buffered) ---------
// mode 0: C = alpha * acc
// mode 1: scores epilogue + fused causal row sums into p3 (atomics)
// mode 2: row scale by p1[m]; K limited to tileM+128 (A lower-tri)
#define BM 128
#define BN 128
#define BK 16
#define ASTR 20    // BK + 4
#define BSTR 136   // BN + 8 (mod 32 == 8 -> conflict-free NN frag loads)

__global__ __launch_bounds__(256)
void tgemm_kernel(int M, int N, int K,
                  const float* __restrict__ A, int lda, long long sAb, long long sAn,
                  const float* __restrict__ B, int ldb, long long sBb, long long sBn,
                  float* __restrict__ C, int ldc, long long sCb, long long sCn,
                  int nhd, int transB, int mode, float alpha,
                  const float* __restrict__ p1, const float* __restrict__ p2,
                  float* __restrict__ p3, int pstr)
{
    const int z  = blockIdx.z;
    const int zb = z / nhd, zn = z % nhd;
    A += zb * sAb + zn * sAn;
    B += zb * sBb + zn * sBn;
    C += zb * sCb + zn * sCn;

    const int tileM = blockIdx.y * BM;
    const int tileN = blockIdx.x * BN;
    if (mode == 1 && tileN > tileM + BM - 1) return;   // fully masked tile

    const int t    = threadIdx.x;
    const int lane = t & 31;
    const int warp = t >> 5;
    const int g    = lane >> 2;     // 0..7
    const int t4   = lane & 3;      // 0..3
    const int wm   = (warp & 1) * 64;
    const int wn   = (warp >> 1) * 32;

    __shared__ float As[2][BM * ASTR];
    __shared__ float Bs[2][BM * ASTR + 128];  // NT: 128*20; NN: 16*136 ok

    float acc[4][4][4];
#pragma unroll
    for (int i = 0; i < 4; i++)
#pragma unroll
        for (int j = 0; j < 4; j++)
#pragma unroll
            for (int r = 0; r < 4; r++) acc[i][j][r] = 0.f;

    int Kend = K;
    if (mode == 2) { int lim = tileM + BM; Kend = lim < K ? lim : K; }
    const int nIter = Kend / BK;

    uint32_t sA[2], sB[2];
    sA[0] = (uint32_t)__cvta_generic_to_shared(&As[0][0]);
    sA[1] = (uint32_t)__cvta_generic_to_shared(&As[1][0]);
    sB[0] = (uint32_t)__cvta_generic_to_shared(&Bs[0][0]);
    sB[1] = (uint32_t)__cvta_generic_to_shared(&Bs[1][0]);

    auto loadTiles = [&](int stg, int k0) {
#pragma unroll
        for (int hh = 0; hh < 2; hh++) {
            int c   = t + hh * 256;
            int row = c >> 2;
            int kc  = (c & 3) * 4;
            const float* gp = &A[(long long)(tileM + row) * lda + k0 + kc];
            cp16(sA[stg] + (row * ASTR + kc) * 4, gp, 16);
        }
        if (!transB) {
#pragma unroll
            for (int hh = 0; hh < 2; hh++) {
                int c  = t + hh * 256;
                int kr = c >> 5;
                int n4 = (c & 31) * 4;
                int gn = tileN + n4;
                int ok = (gn < N);
                const float* gp = &B[(long long)(k0 + kr) * ldb + (ok ? gn : 0)];
                cp16(sB[stg] + (kr * BSTR + n4) * 4, gp, ok ? 16 : 0);
            }
        } else {
#pragma unroll
            for (int hh = 0; hh < 2; hh++) {
                int c   = t + hh * 256;
                int row = c >> 2;
                int kc  = (c & 3) * 4;
                const float* gp = &B[(long long)(tileN + row) * ldb + k0 + kc];
                cp16(sB[stg] + (row * ASTR + kc) * 4, gp, 16);
            }
        }
        cp_commit();
    };

    loadTiles(0, 0);
    cp_wait0();
    __syncthreads();

    for (int it = 0; it < nIter; it++) {
        const int s  = it & 1;
        const int kn = (it + 1) * BK;
        const bool more = (kn < Kend);
        if (more) loadTiles(s ^ 1, kn);

        const float* Asb = As[s];
        const float* Bsb = Bs[s];
#pragma unroll
        for (int ks = 0; ks < BK; ks += 8) {
            uint32_t af[4][4], bf[4][2];
#pragma unroll
            for (int i = 0; i < 4; i++) {
                int m0 = wm + i * 16 + g;
                af[i][0] = f2tf32(Asb[(m0    ) * ASTR + ks + t4    ]);
                af[i][1] = f2tf32(Asb[(m0 + 8) * ASTR + ks + t4    ]);
                af[i][2] = f2tf32(Asb[(m0    ) * ASTR + ks + t4 + 4]);
                af[i][3] = f2tf32(Asb[(m0 + 8) * ASTR + ks + t4 + 4]);
            }
#pragma unroll
            for (int j = 0; j < 4; j++) {
                int n0 = wn + j * 8 + g;
                if (transB) {
                    bf[j][0] = f2tf32(Bsb[n0 * ASTR + ks + t4    ]);
                    bf[j][1] = f2tf32(Bsb[n0 * ASTR + ks + t4 + 4]);
                } else {
                    bf[j][0] = f2tf32(Bsb[(ks + t4    ) * BSTR + n0]);
                    bf[j][1] = f2tf32(Bsb[(ks + t4 + 4) * BSTR + n0]);
                }
            }
#pragma unroll
            for (int i = 0; i < 4; i++)
#pragma unroll
                for (int j = 0; j < 4; j++)
                    MMA_TF32(acc[i][j], af[i], bf[j]);
        }

        if (more) cp_wait0();
        __syncthreads();
    }

    // ---- epilogue ----
    const long long zoff = (long long)z * pstr;
    float p1v[8];
    if (mode == 1) {
#pragma unroll
        for (int j = 0; j < 4; j++) {
            int gn = tileN + wn + j * 8 + t4 * 2;
            p1v[2 * j]     = p1[zoff + gn];
            p1v[2 * j + 1] = p1[zoff + gn + 1];
        }
    }
#pragma unroll
    for (int i = 0; i < 4; i++) {
        int gmBase = tileM + wm + i * 16 + g;
#pragma unroll
        for (int half = 0; half < 2; half++) {
            int gm = gmBase + half * 8;
            float pmv = 0.f, rsv = 1.f;
            if (mode == 1)      pmv = p2[zoff + gm];
            else if (mode == 2) rsv = p1[zoff + gm];
            float* Crow = C + (long long)gm * ldc;
            float rsum = 0.f;
#pragma unroll
            for (int j = 0; j < 4; j++) {
                int gn = tileN + wn + j * 8 + t4 * 2;
                if (gn >= N) continue;
                float v0 = acc[i][j][half * 2 + 0];
                float v1 = acc[i][j][half * 2 + 1];
                if (mode == 1) {
                    v0 = (gn     <= gm) ? v0 * alpha * __expf(p1v[2 * j    ] - pmv) : 0.f;
                    v1 = (gn + 1 <= gm) ? v1 * alpha * __expf(p1v[2 * j + 1] - pmv) : 0.f;
                    rsum += v0 + v1;
                } else if (mode == 2) {
                    v0 *= rsv; v1 *= rsv;
                } else {
                    v0 *= alpha; v1 *= alpha;
                }
                *reinterpret_cast<float2*>(&Crow[gn]) = make_float2(v0, v1);
            }
            if (mode == 1) {
                rsum += __shfl_xor_sync(0xffffffffu, rsum, 1);
                rsum += __shfl_xor_sync(0xffffffffu, rsum, 2);
                if (t4 == 0) atomicAdd(&p3[zoff + gm], rsum);
            }
        }
    }
}

// ---------------- depthwise causal conv + SiLU (xm in xmz, stride 2H) ------
__global__ void conv_silu_kernel(const float* __restrict__ xmz,
                                 const float* __restrict__ w,
                                 const float* __restrict__ bias,
                                 float* __restrict__ xca)
{
    long long idx = (long long)blockIdx.x * blockDim.x + threadIdx.x;
    if (idx >= cBSH) return;
    int h = (int)(idx % cH);
    long long bs = idx / cH;
    int s = (int)(bs % cS);
    long long rowbase = (bs - s) * c2H + h;
    float acc = bias[h];
#pragma unroll
    for (int tt = 0; tt < cKS; tt++) {
        int sp = s - (cKS - 1) + tt;
        if (sp >= 0) acc += xmz[rowbase + (long long)sp * c2H] * w[tt * cH + h];
    }
    float sg = 1.f / (1.f + __expf(-acc));
    xca[idx] = acc * sg;
}

// ---------------- headwise 4x4 projections ----------------
__global__ void headwise_kernel(const float* __restrict__ xca,
                                const float* __restrict__ xmz,
                                const float* __restrict__ Wq,
                                const float* __restrict__ Wk,
                                const float* __restrict__ Wv,
                                float* __restrict__ q,
                                float* __restrict__ k,
                                float* __restrict__ v)
{
    long long idx = (long long)blockIdx.x * blockDim.x + threadIdx.x;
    long long total = cBS * (long long)cNPH;
    if (idx >= total) return;
    int p = (int)(idx % cNPH);
    long long bs = idx / cNPH;
    long long base = bs * cH + p * 4;
    float4 xa = *reinterpret_cast<const float4*>(xca + base);
    float4 xv = *reinterpret_cast<const float4*>(xmz + bs * c2H + p * 4);
    const float4* wq4 = reinterpret_cast<const float4*>(Wq + p * 16);
    const float4* wk4 = reinterpret_cast<const float4*>(Wk + p * 16);
    const float4* wv4 = reinterpret_cast<const float4*>(Wv + p * 16);
    float4 q0 = wq4[0], q1 = wq4[1], q2 = wq4[2], q3 = wq4[3];
    float4 k0 = wk4[0], k1 = wk4[1], k2 = wk4[2], k3 = wk4[3];
    float4 v0 = wv4[0], v1 = wv4[1], v2 = wv4[2], v3 = wv4[3];
    float4 qo, ko, vo;
    qo.x = xa.x*q0.x + xa.y*q1.x + xa.z*q2.x + xa.w*q3.x;
    qo.y = xa.x*q0.y + xa.y*q1.y + xa.z*q2.y + xa.w*q3.y;
    qo.z = xa.x*q0.z + xa.y*q1.z + xa.z*q2.z + xa.w*q3.z;
    qo.w = xa.x*q0.w + xa.y*q1.w + xa.z*q2.w + xa.w*q3.w;
    ko.x = xa.x*k0.x + xa.y*k1.x + xa.z*k2.x + xa.w*k3.x;
    ko.y = xa.x*k0.y + xa.y*k1.y + xa.z*k2.y + xa.w*k3.y;
    ko.z = xa.x*k0.z + xa.y*k1.z + xa.z*k2.z + xa.w*k3.z;
    ko.w = xa.x*k0.w + xa.y*k1.w + xa.z*k2.w + xa.w*k3.w;
    vo.x = xv.x*v0.x + xv.y*v1.x + xv.z*v2.x + xv.w*v3.x;
    vo.y = xv.x*v0.y + xv.y*v1.y + xv.z*v2.y + xv.w*v3.y;
    vo.z = xv.x*v0.z + xv.y*v1.z + xv.z*v2.z + xv.w*v3.z;
    vo.w = xv.x*v0.w + xv.y*v1.w + xv.z*v2.w + xv.w*v3.w;
    *reinterpret_cast<float4*>(q + base) = qo;
    *reinterpret_cast<float4*>(k + base) = ko;
    *reinterpret_cast<float4*>(v + base) = vo;
}

// ---------------- gate projections: warp-per-4-rows GEMV ----------------
#define GW_ROWS 4     // rows per warp
__global__ __launch_bounds__(256)
void gates_kernel(const float* __restrict__ q, const float* __restrict__ k,
                  const float* __restrict__ v,
                  const float* __restrict__ Wig, const float* __restrict__ big,
                  const float* __restrict__ Wfg, const float* __restrict__ bfg,
                  float* __restrict__ ipre, float* __restrict__ fpre)
{
    const int warp = threadIdx.x >> 5;
    const int lane = threadIdx.x & 31;
    const long long row0 = (long long)blockIdx.x * (8 * GW_ROWS) + warp * GW_ROWS;

    float ai[GW_ROWS][4], af[GW_ROWS][4];
#pragma unroll
    for (int rw = 0; rw < GW_ROWS; rw++)
#pragma unroll
        for (int n = 0; n < 4; n++) { ai[rw][n] = 0.f; af[rw][n] = 0.f; }

    for (int r = lane; r < 3 * cH; r += 32) {
        float4 wi = *reinterpret_cast<const float4*>(Wig + (long long)r * 4);
        float4 wf = *reinterpret_cast<const float4*>(Wfg + (long long)r * 4);
        const float* src;
        int col;
        if (r < cH)          { src = q; col = r; }
        else if (r < 2 * cH) { src = k; col = r - cH; }
        else                 { src = v; col = r - 2 * cH; }
#pragma unroll
        for (int rw = 0; rw < GW_ROWS; rw++) {
            float val = src[(row0 + rw) * cH + col];
            ai[rw][0] += val * wi.x; ai[rw][1] += val * wi.y;
            ai[rw][2] += val * wi.z; ai[rw][3] += val * wi.w;
            af[rw][0] += val * wf.x; af[rw][1] += val * wf.y;
            af[rw][2] += val * wf.z; af[rw][3] += val * wf.w;
        }
    }

    // warp reduce all 8*GW_ROWS accumulators
#pragma unroll
    for (int o = 16; o > 0; o >>= 1) {
#pragma unroll
        for (int rw = 0; rw < GW_ROWS; rw++)
#pragma unroll
            for (int n = 0; n < 4; n++) {
                ai[rw][n] += __shfl_xor_sync(0xffffffffu, ai[rw][n], o);
                af[rw][n] += __shfl_xor_sync(0xffffffffu, af[rw][n], o);
            }
    }
    if (lane == 0) {
#pragma unroll
        for (int rw = 0; rw < GW_ROWS; rw++) {
            long long bs = row0 + rw;
            int b = (int)(bs / cS), s = (int)(bs % cS);
#pragma unroll
            for (int n = 0; n < 4; n++) {
                ipre[(long long)(b * cNH + n) * cS + s] = ai[rw][n] + big[n];
                fpre[(long long)(b * cNH + n) * cS + s] = af[rw][n] + bfg[n];
            }
        }
    }
}

// ---------------- scan: cumsum(logsigmoid(f)), a = i - cs, prefix-max(a) ----
__global__ __launch_bounds__(256)
void scan_kernel(const float* __restrict__ ipre, const float* __restrict__ fpre,
                 float* __restrict__ cs, float* __restrict__ aArr,
                 float* __restrict__ pm, float* __restrict__ nsum)
{
    int bh = blockIdx.x;
    int t  = threadIdx.x;
    const float* fp = fpre + (long long)bh * cS;
    const float* ip = ipre + (long long)bh * cS;

    float loc[8];
    float sum = 0.f;
#pragma unroll
    for (int u = 0; u < 8; u++) {
        int j = t * 8 + u;
        float f = fp[j];
        float lf = fminf(f, 0.f) - log1pf(expf(-fabsf(f)));
        sum += lf;
        loc[u] = sum;
    }
    __shared__ float part[256];
    part[t] = sum;
    __syncthreads();
    for (int off = 1; off < 256; off <<= 1) {
        float vv = (t >= off) ? part[t - off] : 0.f;
        __syncthreads();
        part[t] += vv;
        __syncthreads();
    }
    float excl = part[t] - sum;

    float lmax[8];
    float amax = -1e30f;
#pragma unroll
    for (int u = 0; u < 8; u++) {
        int j = t * 8 + u;
        float csj = excl + loc[u];
        cs[(long long)bh * cS + j] = csj;
        float aj = ip[j] - csj;
        aArr[(long long)bh * cS + j] = aj;
        nsum[(long long)bh * cS + j] = 0.f;
        amax = fmaxf(amax, aj);
        lmax[u] = amax;
    }
    __syncthreads();
    part[t] = amax;
    __syncthreads();
    for (int off = 1; off < 256; off <<= 1) {
        float vv = (t >= off) ? part[t - off] : -1e30f;
        __syncthreads();
        part[t] = fmaxf(part[t], vv);
        __syncthreads();
    }
    float exmax = (t > 0) ? part[t - 1] : -1e30f;
#pragma unroll
    for (int u = 0; u < 8; u++) {
        int j = t * 8 + u;
        pm[(long long)bh * cS + j] = fmaxf(exmax, lmax[u]);
    }
}

// ---------------- finalize n -> rs ----------------
__global__ void nfin_kernel(const float* __restrict__ nsum,
                            const float* __restrict__ cs, const float* __restrict__ pm,
                            float* __restrict__ rs)
{
    int idx = blockIdx.x * blockDim.x + threadIdx.x;
    if (idx >= cBHS) return;
    float m = cs[idx] + pm[idx];
    float n = fmaxf(fabsf(nsum[idx]), __expf(-m));
    rs[idx] = 1.f / (n + 1e-6f);
}

// ---------------- multi-head LN + skip + z-gate ----------------
__global__ __launch_bounds__(256)
void ln_kernel(const float* __restrict__ hbuf, const float* __restrict__ xca,
               const float* __restrict__ xmz, const float* __restrict__ norm_w,
               const float* __restrict__ skip, float* __restrict__ hs)
{
    int s  = blockIdx.x;
    int bh = blockIdx.y;
    int t  = threadIdx.x;
    int b = bh / cNH, n = bh % cNH;
    const float* hrow = hbuf + ((long long)bh * cS + s) * cDH;

    float sum = 0.f, ss = 0.f;
    for (int d = t; d < cDH; d += 256) {
        float v = hrow[d];
        sum += v; ss += v * v;
    }
    __shared__ float r1[256], r2[256];
    r1[t] = sum; r2[t] = ss;
    __syncthreads();
    for (int o = 128; o > 0; o >>= 1) {
        if (t < o) { r1[t] += r1[t + o]; r2[t] += r2[t + o]; }
        __syncthreads();
    }
    float mean = r1[0] / cDH;
    float var  = r2[0] / cDH - mean * mean;
    float inv  = rsqrtf(var + 1e-5f);

    long long bsRow = (long long)b * cS + s;
    long long xbase = bsRow * cH;
    long long zbase = bsRow * c2H + cH;
    for (int d = t; d < cDH; d += 256) {
        int col = n * cDH + d;
        float hn = (hrow[d] - mean) * inv * norm_w[col];
        float hk = hn + skip[col] * xca[xbase + col];
        float zv = xmz[zbase + col];
        float sz = zv / (1.f + __expf(-zv));
        hs[xbase + col] = hk * sz;
    }
}

// ---------------- launch ----------------
extern "C" void kernel_launch(void* const* d_in, const int* in_sizes, int n_in,
                              void* d_out, int out_size)
{
    const float* x      = (const float*)d_in[0];
    const float* W_in   = (const float*)d_in[1];
    const float* conv_w = (const float*)d_in[2];
    const float* conv_b = (const float*)d_in[3];
    const float* Wq     = (const float*)d_in[4];
    const float* Wk     = (const float*)d_in[5];
    const float* Wv     = (const float*)d_in[6];
    const float* W_ig   = (const float*)d_in[7];
    const float* b_ig   = (const float*)d_in[8];
    const float* W_fg   = (const float*)d_in[9];
    const float* b_fg   = (const float*)d_in[10];
    const float* norm_w = (const float*)d_in[11];
    const float* skip   = (const float*)d_in[12];
    const float* W_out  = (const float*)d_in[13];
    float* out = (float*)d_out;

    float *p_xmz, *p_xca, *p_q, *p_k, *p_v, *p_h, *p_hs, *p_sc;
    float *p_ipre, *p_fpre, *p_cs, *p_a, *p_pm, *p_rs, *p_ns;
    cudaGetSymbolAddress((void**)&p_xmz, g_xmz);
    cudaGetSymbolAddress((void**)&p_xca, g_xca);
    cudaGetSymbolAddress((void**)&p_q,   g_q);
    cudaGetSymbolAddress((void**)&p_k,   g_k);
    cudaGetSymbolAddress((void**)&p_v,   g_v);
    cudaGetSymbolAddress((void**)&p_h,   g_h);
    cudaGetSymbolAddress((void**)&p_hs,  g_hs);
    cudaGetSymbolAddress((void**)&p_sc,  g_scores);
    cudaGetSymbolAddress((void**)&p_ipre, g_ipre);
    cudaGetSymbolAddress((void**)&p_fpre, g_fpre);
    cudaGetSymbolAddress((void**)&p_cs,  g_cs);
    cudaGetSymbolAddress((void**)&p_a,   g_a);
    cudaGetSymbolAddress((void**)&p_pm,  g_pm);
    cudaGetSymbolAddress((void**)&p_rs,  g_rs);
    cudaGetSymbolAddress((void**)&p_ns,  g_nsum);

    const int M0 = (int)cBS;  // 4096

    // 1) x @ W_in -> xmz (single merged GEMM, N = 2H)
    {
        dim3 grid(c2H / BN, M0 / BM, 1);
        tgemm_kernel<<<grid, 256>>>(M0, c2H, cE,
            x, cE, 0, 0,
            W_in, c2H, 0, 0,
            p_xmz, c2H, 0, 0,
            1, 0, 0, 1.0f, nullptr, nullptr, nullptr, 0);
    }

    // 2) depthwise causal conv + SiLU
    {
        long long total = cBSH;
        int blocks = (int)((total + 255) / 256);
        conv_silu_kernel<<<blocks, 256>>>(p_xmz, conv_w, conv_b, p_xca);
    }

    // 3) headwise q/k/v
    {
        long long total = cBS * (long long)cNPH;
        int blocks = (int)((total + 255) / 256);
        headwise_kernel<<<blocks, 256>>>(p_xca, p_xmz, Wq, Wk, Wv, p_q, p_k, p_v);
    }

    // 4) gates (32 rows per block, 8 warps x 4 rows)
    gates_kernel<<<M0 / (8 * GW_ROWS), 256>>>(p_q, p_k, p_v, W_ig, b_ig, W_fg, b_fg, p_ipre, p_fpre);

    // 5) scan (also zeroes nsum)
    scan_kernel<<<cB * cNH, 256>>>(p_ipre, p_fpre, p_cs, p_a, p_pm, p_ns);

    // 6) scores = (q k^T / sqrt(DH)) * exp(a_j - pm_i), causal, + fused row sums
    {
        dim3 grid(cS / BN, cS / BM, cB * cNH);
        float alpha = 1.0f / sqrtf((float)cDH);
        tgemm_kernel<<<grid, 256>>>(cS, cS, cDH,
            p_q, cH, (long long)cS * cH, (long long)cDH,
            p_k, cH, (long long)cS * cH, (long long)cDH,
            p_sc, cS, (long long)cNH * cS * cS, (long long)cS * cS,
            cNH, 1, 1, alpha, p_a, p_pm, p_ns, cS);
    }

    // 7) finalize rs
    nfin_kernel<<<(cBHS + 255) / 256, 256>>>(p_ns, p_cs, p_pm, p_rs);

    // 8) h = diag(rs) * scores @ v   (causal K-limit)
    {
        dim3 grid((cDH + BN - 1) / BN, cS / BM, cB * cNH);
        tgemm_kernel<<<grid, 256>>>(cS, cDH, cS,
            p_sc, cS, (long long)cNH * cS * cS, (long long)cS * cS,
            p_v, cH, (long long)cS * cH, (long long)cDH,
            p_h, cDH, (long long)cNH * cS * cDH, (long long)cS * cDH,
            cNH, 0, 2, 1.0f, p_rs, nullptr, nullptr, cS);
    }

    // 9) LN + skip + z gate
    {
        dim3 grid(cS, cB * cNH);
        ln_kernel<<<grid, 256>>>(p_h, p_xca, p_xmz, norm_w, skip, p_hs);
    }

    // 10) out = hs @ W_out
    {
        dim3 grid(cE / BN, M0 / BM, 1);
        tgemm_kernel<<<grid, 256>>>(M0, cE, cH,
            p_hs, cH, 0, 0,
            W_out, cE, 0, 0,
            out, cE, 0, 0,
            1, 0, 0, 1.0f, nullptr, nullptr, nullptr, 0);
    }
}

// round 6
// speedup vs baseline: 1.0689x; 1.0233x over previous
#include <cuda_runtime.h>
#include <math.h>
#include <stdint.h>

// ---------------- problem dims ----------------
constexpr int cB   = 2;
constexpr int cS   = 2048;
constexpr int cE   = 2048;
constexpr int cH   = 2688;
constexpr int c2H  = 2 * cH;
constexpr int cNH  = 4;
constexpr int cDH  = 672;   // cH / cNH
constexpr int cKS  = 4;
constexpr int cNPH = 672;   // cH / 4
constexpr long long cBS  = (long long)cB * cS;        // 4096
constexpr long long cBSH = cBS * cH;                  // 11,010,048
constexpr long long cSCORES = (long long)cB * cNH * cS * cS; // 33,554,432
constexpr int cBHS = cB * cNH * cS;                   // 16384
constexpr int c3H  = 3 * cH;                          // 8064
constexpr int cHALF = c3H / 2;                        // 4032

// ---------------- device scratch ----------------
__device__ float g_xmz[cBS * (long long)c2H];   // [BS][2H]: xm | z
__device__ float g_xca[cBSH];
__device__ float g_q  [cBSH];
__device__ float g_k  [cBSH];
__device__ float g_v  [cBSH];
__device__ float g_h  [cBSH];
__device__ float g_hs [cBSH];
__device__ float g_scores[cSCORES];
__device__ float g_ipre[cBHS];
__device__ float g_fpre[cBHS];
__device__ float g_cs  [cBHS];
__device__ float g_a   [cBHS];
__device__ float g_pm  [cBHS];
__device__ float g_rs  [cBHS];
__device__ float g_nsum[cBHS];

// ---------------- helpers ----------------
__device__ __forceinline__ uint32_t f2tf32(float x) {
    uint32_t r;
    asm("cvt.rna.tf32.f32 %0, %1;" : "=r"(r) : "f"(x));
    return r;
}

__device__ __forceinline__ void cp16(uint32_t saddr, const void* gptr, int bytes) {
    asm volatile("cp.async.cg.shared.global [%0], [%1], 16, %2;\n"
                 :: "r"(saddr), "l"(gptr), "r"(bytes));
}
__device__ __forceinline__ void cp_commit() { asm volatile("cp.async.commit_group;\n" ::: "memory"); }
__device__ __forceinline__ void cp_wait0()  { asm volatile("cp.async.wait_group 0;\n" ::: "memory"); }

#define MMA_TF32(d, a, b)                                                      \
    asm volatile(                                                              \
        "mma.sync.aligned.m16n8k8.row.col.f32.tf32.tf32.f32 "                  \
        "{%0,%1,%2,%3},{%4,%5,%6,%7},{%8,%9},{%0,%1,%2,%3};\n"                 \
        : "+f"(d[0]), "+f"(d[1]), "+f"(d[2]), "+f"(d[3])                       \
        : "r"(a[0]), "r"(a[1]), "r"(a[2]), "r"(a[3]), "r"(b[0]), "r"(b[1]))

// ---------------- tf32 tensor-core GEMM (cp.async double buffered) ---------
// mode 0: C = alpha * acc
// mode 1: scores epilogue + fused causal row sums into p3 (atomics)
// mode 2: row scale by p1[m]; K limited to tileM+128 (A lower-tri)
#define BM 128
#define BN 128
#define BK 16
#define ASTR 20    // BK + 4
#define BSTR 136   // BN + 8 (mod 32 == 8 -> conflict-free NN frag loads)

__global__ __launch_bounds__(256)
void tgemm_kernel(int M, int N, int K,
                  const float* __restrict__ A, int lda, long long sAb, long long sAn,
                  const float* __restrict__ B, int ldb, long long sBb, long long sBn,
                  float* __restrict__ C, int ldc, long long sCb, long long sCn,
                  int nhd, int transB, int mode, float alpha,
                  const float* __restrict__ p1, const float* __restrict__ p2,
                  float* __restrict__ p3, int pstr)
{
    const int z  = blockIdx.z;
    const int zb = z / nhd, zn = z % nhd;
    A += zb * sAb + zn * sAn;
    B += zb * sBb + zn * sBn;
    C += zb * sCb + zn * sCn;

    const int tileM = blockIdx.y * BM;
    const int tileN = blockIdx.x * BN;
    if (mode == 1 && tileN > tileM + BM - 1) return;   // fully masked tile

    const int t    = threadIdx.x;
    const int lane = t & 31;
    const int warp = t >> 5;
    const int g    = lane >> 2;     // 0..7
    const int t4   = lane & 3;      // 0..3
    const int wm   = (warp & 1) * 64;
    const int wn   = (warp >> 1) * 32;

    __shared__ float As[2][BM * ASTR];
    __shared__ float Bs[2][BM * ASTR + 128];  // NT: 128*20; NN: 16*136 ok

    float acc[4][4][4];
#pragma unroll
    for (int i = 0; i < 4; i++)
#pragma unroll
        for (int j = 0; j < 4; j++)
#pragma unroll
            for (int r = 0; r < 4; r++) acc[i][j][r] = 0.f;

    int Kend = K;
    if (mode == 2) { int lim = tileM + BM; Kend = lim < K ? lim : K; }
    const int nIter = Kend / BK;

    uint32_t sA[2], sB[2];
    sA[0] = (uint32_t)__cvta_generic_to_shared(&As[0][0]);
    sA[1] = (uint32_t)__cvta_generic_to_shared(&As[1][0]);
    sB[0] = (uint32_t)__cvta_generic_to_shared(&Bs[0][0]);
    sB[1] = (uint32_t)__cvta_generic_to_shared(&Bs[1][0]);

    auto loadTiles = [&](int stg, int k0) {
#pragma unroll
        for (int hh = 0; hh < 2; hh++) {
            int c   = t + hh * 256;
            int row = c >> 2;
            int kc  = (c & 3) * 4;
            const float* gp = &A[(long long)(tileM + row) * lda + k0 + kc];
            cp16(sA[stg] + (row * ASTR + kc) * 4, gp, 16);
        }
        if (!transB) {
#pragma unroll
            for (int hh = 0; hh < 2; hh++) {
                int c  = t + hh * 256;
                int kr = c >> 5;
                int n4 = (c & 31) * 4;
                int gn = tileN + n4;
                int ok = (gn < N);
                const float* gp = &B[(long long)(k0 + kr) * ldb + (ok ? gn : 0)];
                cp16(sB[stg] + (kr * BSTR + n4) * 4, gp, ok ? 16 : 0);
            }
        } else {
#pragma unroll
            for (int hh = 0; hh < 2; hh++) {
                int c   = t + hh * 256;
                int row = c >> 2;
                int kc  = (c & 3) * 4;
                const float* gp = &B[(long long)(tileN + row) * ldb + k0 + kc];
                cp16(sB[stg] + (row * ASTR + kc) * 4, gp, 16);
            }
        }
        cp_commit();
    };

    loadTiles(0, 0);
    cp_wait0();
    __syncthreads();

    for (int it = 0; it < nIter; it++) {
        const int s  = it & 1;
        const int kn = (it + 1) * BK;
        const bool more = (kn < Kend);
        if (more) loadTiles(s ^ 1, kn);

        const float* Asb = As[s];
        const float* Bsb = Bs[s];
#pragma unroll
        for (int ks = 0; ks < BK; ks += 8) {
            uint32_t af[4][4], bf[4][2];
#pragma unroll
            for (int i = 0; i < 4; i++) {
                int m0 = wm + i * 16 + g;
                af[i][0] = f2tf32(Asb[(m0    ) * ASTR + ks + t4    ]);
                af[i][1] = f2tf32(Asb[(m0 + 8) * ASTR + ks + t4    ]);
                af[i][2] = f2tf32(Asb[(m0    ) * ASTR + ks + t4 + 4]);
                af[i][3] = f2tf32(Asb[(m0 + 8) * ASTR + ks + t4 + 4]);
            }
#pragma unroll
            for (int j = 0; j < 4; j++) {
                int n0 = wn + j * 8 + g;
                if (transB) {
                    bf[j][0] = f2tf32(Bsb[n0 * ASTR + ks + t4    ]);
                    bf[j][1] = f2tf32(Bsb[n0 * ASTR + ks + t4 + 4]);
                } else {
                    bf[j][0] = f2tf32(Bsb[(ks + t4    ) * BSTR + n0]);
                    bf[j][1] = f2tf32(Bsb[(ks + t4 + 4) * BSTR + n0]);
                }
            }
#pragma unroll
            for (int i = 0; i < 4; i++)
#pragma unroll
                for (int j = 0; j < 4; j++)
                    MMA_TF32(acc[i][j], af[i], bf[j]);
        }

        if (more) cp_wait0();
        __syncthreads();
    }

    // ---- epilogue ----
    const long long zoff = (long long)z * pstr;
    float p1v[8];
    if (mode == 1) {
#pragma unroll
        for (int j = 0; j < 4; j++) {
            int gn = tileN + wn + j * 8 + t4 * 2;
            p1v[2 * j]     = p1[zoff + gn];
            p1v[2 * j + 1] = p1[zoff + gn + 1];
        }
    }
#pragma unroll
    for (int i = 0; i < 4; i++) {
        int gmBase = tileM + wm + i * 16 + g;
#pragma unroll
        for (int half = 0; half < 2; half++) {
            int gm = gmBase + half * 8;
            float pmv = 0.f, rsv = 1.f;
            if (mode == 1)      pmv = p2[zoff + gm];
            else if (mode == 2) rsv = p1[zoff + gm];
            float* Crow = C + (long long)gm * ldc;
            float rsum = 0.f;
#pragma unroll
            for (int j = 0; j < 4; j++) {
                int gn = tileN + wn + j * 8 + t4 * 2;
                if (gn >= N) continue;
                float v0 = acc[i][j][half * 2 + 0];
                float v1 = acc[i][j][half * 2 + 1];
                if (mode == 1) {
                    v0 = (gn     <= gm) ? v0 * alpha * __expf(p1v[2 * j    ] - pmv) : 0.f;
                    v1 = (gn + 1 <= gm) ? v1 * alpha * __expf(p1v[2 * j + 1] - pmv) : 0.f;
                    rsum += v0 + v1;
                } else if (mode == 2) {
                    v0 *= rsv; v1 *= rsv;
                } else {
                    v0 *= alpha; v1 *= alpha;
                }
                *reinterpret_cast<float2*>(&Crow[gn]) = make_float2(v0, v1);
            }
            if (mode == 1) {
                rsum += __shfl_xor_sync(0xffffffffu, rsum, 1);
                rsum += __shfl_xor_sync(0xffffffffu, rsum, 2);
                if (t4 == 0) atomicAdd(&p3[zoff + gm], rsum);
            }
        }
    }
}

// ---------------- fused depthwise conv + SiLU + headwise q/k/v -------------
__global__ void convhead_kernel(const float* __restrict__ xmz,
                                const float* __restrict__ w,
                                const float* __restrict__ bias,
                                const float* __restrict__ Wq,
                                const float* __restrict__ Wk,
                                const float* __restrict__ Wv,
                                float* __restrict__ xca,
                                float* __restrict__ q,
                                float* __restrict__ k,
                                float* __restrict__ v)
{
    long long idx = (long long)blockIdx.x * blockDim.x + threadIdx.x;
    long long total = cBS * (long long)cNPH;
    if (idx >= total) return;
    int p = (int)(idx % cNPH);
    long long bs = idx / cNPH;
    int s = (int)(bs % cS);
    int col = p * 4;

    // load 4 conv taps (rows bs-3..bs of xm slice), zero above sequence start
    float4 xr[cKS];
#pragma unroll
    for (int tt = 0; tt < cKS; tt++) {
        int sp = s - (cKS - 1) + tt;
        if (sp >= 0)
            xr[tt] = *reinterpret_cast<const float4*>(xmz + (bs - (cKS - 1) + tt) * c2H + col);
        else
            xr[tt] = make_float4(0.f, 0.f, 0.f, 0.f);
    }
    float4 wt[cKS];
#pragma unroll
    for (int tt = 0; tt < cKS; tt++)
        wt[tt] = *reinterpret_cast<const float4*>(w + tt * cH + col);
    float4 bb = *reinterpret_cast<const float4*>(bias + col);

    float4 xc;
    xc.x = bb.x + xr[0].x*wt[0].x + xr[1].x*wt[1].x + xr[2].x*wt[2].x + xr[3].x*wt[3].x;
    xc.y = bb.y + xr[0].y*wt[0].y + xr[1].y*wt[1].y + xr[2].y*wt[2].y + xr[3].y*wt[3].y;
    xc.z = bb.z + xr[0].z*wt[0].z + xr[1].z*wt[1].z + xr[2].z*wt[2].z + xr[3].z*wt[3].z;
    xc.w = bb.w + xr[0].w*wt[0].w + xr[1].w*wt[1].w + xr[2].w*wt[2].w + xr[3].w*wt[3].w;
    // SiLU
    xc.x = xc.x / (1.f + __expf(-xc.x));
    xc.y = xc.y / (1.f + __expf(-xc.y));
    xc.z = xc.z / (1.f + __expf(-xc.z));
    xc.w = xc.w / (1.f + __expf(-xc.w));

    long long base = bs * cH + col;
    *reinterpret_cast<float4*>(xca + base) = xc;

    float4 xv = xr[cKS - 1];   // row bs of xm (v uses pre-conv x_m)

    const float4* wq4 = reinterpret_cast<const float4*>(Wq + p * 16);
    const float4* wk4 = reinterpret_cast<const float4*>(Wk + p * 16);
    const float4* wv4 = reinterpret_cast<const float4*>(Wv + p * 16);
    float4 q0 = wq4[0], q1 = wq4[1], q2 = wq4[2], q3 = wq4[3];
    float4 k0 = wk4[0], k1 = wk4[1], k2 = wk4[2], k3 = wk4[3];
    float4 v0 = wv4[0], v1 = wv4[1], v2 = wv4[2], v3 = wv4[3];
    float4 qo, ko, vo;
    qo.x = xc.x*q0.x + xc.y*q1.x + xc.z*q2.x + xc.w*q3.x;
    qo.y = xc.x*q0.y + xc.y*q1.y + xc.z*q2.y + xc.w*q3.y;
    qo.z = xc.x*q0.z + xc.y*q1.z + xc.z*q2.z + xc.w*q3.z;
    qo.w = xc.x*q0.w + xc.y*q1.w + xc.z*q2.w + xc.w*q3.w;
    ko.x = xc.x*k0.x + xc.y*k1.x + xc.z*k2.x + xc.w*k3.x;
    ko.y = xc.x*k0.y + xc.y*k1.y + xc.z*k2.y + xc.w*k3.y;
    ko.z = xc.x*k0.z + xc.y*k1.z + xc.z*k2.z + xc.w*k3.z;
    ko.w = xc.x*k0.w + xc.y*k1.w + xc.z*k2.w + xc.w*k3.w;
    vo.x = xv.x*v0.x + xv.y*v1.x + xv.z*v2.x + xv.w*v3.x;
    vo.y = xv.x*v0.y + xv.y*v1.y + xv.z*v2.y + xv.w*v3.y;
    vo.z = xv.x*v0.z + xv.y*v1.z + xv.z*v2.z + xv.w*v3.z;
    vo.w = xv.x*v0.w + xv.y*v1.w + xv.z*v2.w + xv.w*v3.w;
    *reinterpret_cast<float4*>(q + base) = qo;
    *reinterpret_cast<float4*>(k + base) = ko;
    *reinterpret_cast<float4*>(v + base) = vo;
}

// ---------------- gates: 4 rows/block, warp = (row, K-half) ----------------
__global__ __launch_bounds__(256)
void gates_kernel(const float* __restrict__ q, const float* __restrict__ k,
                  const float* __restrict__ v,
                  const float* __restrict__ Wig, const float* __restrict__ big,
                  const float* __restrict__ Wfg, const float* __restrict__ bfg,
                  float* __restrict__ ipre, float* __restrict__ fpre)
{
    const int warp = threadIdx.x >> 5;
    const int lane = threadIdx.x & 31;
    const int rw   = warp >> 1;          // 0..3 local row
    const int half = warp & 1;           // K half
    const long long row = (long long)blockIdx.x * 4 + rw;

    float ai[4] = {0, 0, 0, 0}, af[4] = {0, 0, 0, 0};
    const int rbeg = half * cHALF;
    const int rend = rbeg + cHALF;
    const long long rbase = row * cH;

    for (int r = rbeg + lane; r < rend; r += 32) {
        float4 wi = *reinterpret_cast<const float4*>(Wig + (long long)r * 4);
        float4 wf = *reinterpret_cast<const float4*>(Wfg + (long long)r * 4);
        float val;
        if (r < cH)          val = q[rbase + r];
        else if (r < 2 * cH) val = k[rbase + r - cH];
        else                 val = v[rbase + r - 2 * cH];
        ai[0] += val * wi.x; ai[1] += val * wi.y;
        ai[2] += val * wi.z; ai[3] += val * wi.w;
        af[0] += val * wf.x; af[1] += val * wf.y;
        af[2] += val * wf.z; af[3] += val * wf.w;
    }

#pragma unroll
    for (int o = 16; o > 0; o >>= 1) {
#pragma unroll
        for (int n = 0; n < 4; n++) {
            ai[n] += __shfl_xor_sync(0xffffffffu, ai[n], o);
            af[n] += __shfl_xor_sync(0xffffffffu, af[n], o);
        }
    }

    __shared__ float part[4][8];   // [row][i0..3 | f0..3] from half=1
    if (half == 1 && lane == 0) {
#pragma unroll
        for (int n = 0; n < 4; n++) { part[rw][n] = ai[n]; part[rw][4 + n] = af[n]; }
    }
    __syncthreads();
    if (half == 0 && lane == 0) {
        int b = (int)(row / cS), s = (int)(row % cS);
#pragma unroll
        for (int n = 0; n < 4; n++) {
            ipre[(long long)(b * cNH + n) * cS + s] = ai[n] + part[rw][n]     + big[n];
            fpre[(long long)(b * cNH + n) * cS + s] = af[n] + part[rw][4 + n] + bfg[n];
        }
    }
}

// ---------------- scan: cumsum(logsigmoid(f)), a = i - cs, prefix-max(a) ----
__global__ __launch_bounds__(256)
void scan_kernel(const float* __restrict__ ipre, const float* __restrict__ fpre,
                 float* __restrict__ cs, float* __restrict__ aArr,
                 float* __restrict__ pm, float* __restrict__ nsum)
{
    int bh = blockIdx.x;
    int t  = threadIdx.x;
    const float* fp = fpre + (long long)bh * cS;
    const float* ip = ipre + (long long)bh * cS;

    float loc[8];
    float sum = 0.f;
#pragma unroll
    for (int u = 0; u < 8; u++) {
        int j = t * 8 + u;
        float f = fp[j];
        float lf = fminf(f, 0.f) - log1pf(expf(-fabsf(f)));
        sum += lf;
        loc[u] = sum;
    }
    __shared__ float part[256];
    part[t] = sum;
    __syncthreads();
    for (int off = 1; off < 256; off <<= 1) {
        float vv = (t >= off) ? part[t - off] : 0.f;
        __syncthreads();
        part[t] += vv;
        __syncthreads();
    }
    float excl = part[t] - sum;

    float lmax[8];
    float amax = -1e30f;
#pragma unroll
    for (int u = 0; u < 8; u++) {
        int j = t * 8 + u;
        float csj = excl + loc[u];
        cs[(long long)bh * cS + j] = csj;
        float aj = ip[j] - csj;
        aArr[(long long)bh * cS + j] = aj;
        nsum[(long long)bh * cS + j] = 0.f;
        amax = fmaxf(amax, aj);
        lmax[u] = amax;
    }
    __syncthreads();
    part[t] = amax;
    __syncthreads();
    for (int off = 1; off < 256; off <<= 1) {
        float vv = (t >= off) ? part[t - off] : -1e30f;
        __syncthreads();
        part[t] = fmaxf(part[t], vv);
        __syncthreads();
    }
    float exmax = (t > 0) ? part[t - 1] : -1e30f;
#pragma unroll
    for (int u = 0; u < 8; u++) {
        int j = t * 8 + u;
        pm[(long long)bh * cS + j] = fmaxf(exmax, lmax[u]);
    }
}

// ---------------- finalize n -> rs ----------------
__global__ void nfin_kernel(const float* __restrict__ nsum,
                            const float* __restrict__ cs, const float* __restrict__ pm,
                            float* __restrict__ rs)
{
    int idx = blockIdx.x * blockDim.x + threadIdx.x;
    if (idx >= cBHS) return;
    float m = cs[idx] + pm[idx];
    float n = fmaxf(fabsf(nsum[idx]), __expf(-m));
    rs[idx] = 1.f / (n + 1e-6f);
}

// ---------------- multi-head LN + skip + z-gate ----------------
__global__ __launch_bounds__(256)
void ln_kernel(const float* __restrict__ hbuf, const float* __restrict__ xca,
               const float* __restrict__ xmz, const float* __restrict__ norm_w,
               const float* __restrict__ skip, float* __restrict__ hs)
{
    int s  = blockIdx.x;
    int bh = blockIdx.y;
    int t  = threadIdx.x;
    int b = bh / cNH, n = bh % cNH;
    const float* hrow = hbuf + ((long long)bh * cS + s) * cDH;

    float sum = 0.f, ss = 0.f;
    for (int d = t; d < cDH; d += 256) {
        float v = hrow[d];
        sum += v; ss += v * v;
    }
    __shared__ float r1[256], r2[256];
    r1[t] = sum; r2[t] = ss;
    __syncthreads();
    for (int o = 128; o > 0; o >>= 1) {
        if (t < o) { r1[t] += r1[t + o]; r2[t] += r2[t + o]; }
        __syncthreads();
    }
    float mean = r1[0] / cDH;
    float var  = r2[0] / cDH - mean * mean;
    float inv  = rsqrtf(var + 1e-5f);

    long long bsRow = (long long)b * cS + s;
    long long xbase = bsRow * cH;
    long long zbase = bsRow * c2H + cH;
    for (int d = t; d < cDH; d += 256) {
        int col = n * cDH + d;
        float hn = (hrow[d] - mean) * inv * norm_w[col];
        float hk = hn + skip[col] * xca[xbase + col];
        float zv = xmz[zbase + col];
        float sz = zv / (1.f + __expf(-zv));
        hs[xbase + col] = hk * sz;
    }
}

// ---------------- launch ----------------
extern "C" void kernel_launch(void* const* d_in, const int* in_sizes, int n_in,
                              void* d_out, int out_size)
{
    const float* x      = (const float*)d_in[0];
    const float* W_in   = (const float*)d_in[1];
    const float* conv_w = (const float*)d_in[2];
    const float* conv_b = (const float*)d_in[3];
    const float* Wq     = (const float*)d_in[4];
    const float* Wk     = (const float*)d_in[5];
    const float* Wv     = (const float*)d_in[6];
    const float* W_ig   = (const float*)d_in[7];
    const float* b_ig   = (const float*)d_in[8];
    const float* W_fg   = (const float*)d_in[9];
    const float* b_fg   = (const float*)d_in[10];
    const float* norm_w = (const float*)d_in[11];
    const float* skip   = (const float*)d_in[12];
    const float* W_out  = (const float*)d_in[13];
    float* out = (float*)d_out;

    float *p_xmz, *p_xca, *p_q, *p_k, *p_v, *p_h, *p_hs, *p_sc;
    float *p_ipre, *p_fpre, *p_cs, *p_a, *p_pm, *p_rs, *p_ns;
    cudaGetSymbolAddress((void**)&p_xmz, g_xmz);
    cudaGetSymbolAddress((void**)&p_xca, g_xca);
    cudaGetSymbolAddress((void**)&p_q,   g_q);
    cudaGetSymbolAddress((void**)&p_k,   g_k);
    cudaGetSymbolAddress((void**)&p_v,   g_v);
    cudaGetSymbolAddress((void**)&p_h,   g_h);
    cudaGetSymbolAddress((void**)&p_hs,  g_hs);
    cudaGetSymbolAddress((void**)&p_sc,  g_scores);
    cudaGetSymbolAddress((void**)&p_ipre, g_ipre);
    cudaGetSymbolAddress((void**)&p_fpre, g_fpre);
    cudaGetSymbolAddress((void**)&p_cs,  g_cs);
    cudaGetSymbolAddress((void**)&p_a,   g_a);
    cudaGetSymbolAddress((void**)&p_pm,  g_pm);
    cudaGetSymbolAddress((void**)&p_rs,  g_rs);
    cudaGetSymbolAddress((void**)&p_ns,  g_nsum);

    const int M0 = (int)cBS;  // 4096

    // 1) x @ W_in -> xmz (single merged GEMM, N = 2H)
    {
        dim3 grid(c2H / BN, M0 / BM, 1);
        tgemm_kernel<<<grid, 256>>>(M0, c2H, cE,
            x, cE, 0, 0,
            W_in, c2H, 0, 0,
            p_xmz, c2H, 0, 0,
            1, 0, 0, 1.0f, nullptr, nullptr, nullptr, 0);
    }

    // 2+3) fused depthwise conv + SiLU + headwise q/k/v
    {
        long long total = cBS * (long long)cNPH;
        int blocks = (int)((total + 255) / 256);
        convhead_kernel<<<blocks, 256>>>(p_xmz, conv_w, conv_b, Wq, Wk, Wv,
                                         p_xca, p_q, p_k, p_v);
    }

    // 4) gates (4 rows/block x split-K halves -> 1024 blocks)
    gates_kernel<<<M0 / 4, 256>>>(p_q, p_k, p_v, W_ig, b_ig, W_fg, b_fg, p_ipre, p_fpre);

    // 5) scan (also zeroes nsum)
    scan_kernel<<<cB * cNH, 256>>>(p_ipre, p_fpre, p_cs, p_a, p_pm, p_ns);

    // 6) scores = (q k^T / sqrt(DH)) * exp(a_j - pm_i), causal, + fused row sums
    {
        dim3 grid(cS / BN, cS / BM, cB * cNH);
        float alpha = 1.0f / sqrtf((float)cDH);
        tgemm_kernel<<<grid, 256>>>(cS, cS, cDH,
            p_q, cH, (long long)cS * cH, (long long)cDH,
            p_k, cH, (long long)cS * cH, (long long)cDH,
            p_sc, cS, (long long)cNH * cS * cS, (long long)cS * cS,
            cNH, 1, 1, alpha, p_a, p_pm, p_ns, cS);
    }

    // 7) finalize rs
    nfin_kernel<<<(cBHS + 255) / 256, 256>>>(p_ns, p_cs, p_pm, p_rs);

    // 8) h = diag(rs) * scores @ v   (causal K-limit)
    {
        dim3 grid((cDH + BN - 1) / BN, cS / BM, cB * cNH);
        tgemm_kernel<<<grid, 256>>>(cS, cDH, cS,
            p_sc, cS, (long long)cNH * cS * cS, (long long)cS * cS,
            p_v, cH, (long long)cS * cH, (long long)cDH,
            p_h, cDH, (long long)cNH * cS * cDH, (long long)cS * cDH,
            cNH, 0, 2, 1.0f, p_rs, nullptr, nullptr, cS);
    }

    // 9) LN + skip + z gate
    {
        dim3 grid(cS, cB * cNH);
        ln_kernel<<<grid, 256>>>(p_h, p_xca, p_xmz, norm_w, skip, p_hs);
    }

    // 10) out = hs @ W_out
    {
        dim3 grid(cE / BN, M0 / BM, 1);
        tgemm_kernel<<<grid, 256>>>(M0, cE, cH,
            p_hs, cH, 0, 0,
            W_out, cE, 0, 0,
            out, cE, 0, 0,
            1, 0, 0, 1.0f, nullptr, nullptr, nullptr, 0);
    }
}